// round 15
// baseline (speedup 1.0000x reference)
#include <cuda_runtime.h>
#include <cuda_fp16.h>
#include <cstdint>

#define B 16
#define CI 64
#define CO 64
#define HH 192
#define WW 192
#define KDY 4
#define HID 17
#define GROUPS 8
#define CPG 8
#define PLANE (HH*WW)
#define TEMPERATURE 30.0f
#define EPS 1e-5f
#define SLOPE 0.01f

// padded fp16 x: rows 0..193 (=gy+1), cols 0..199 (=gx+4), halo zero
#define WP 200
#define HP 194
#define PPLANE (HP*WP)

// conv: 4 ci-chunks, 3 col tiles, filters resident per (b, n-half)
#define NCH 4
#define NTILE 3
#define NSTEP (NCH*NTILE)
#define SFB 36864                   // filters: 4cc*9tap*2kh*32n*16B
#define SXHB 13824                  // x tile: 6 rows * 72 px * 32B
#define SX0 SFB
#define SMB (SFB + 2*SXHB)          // mbF, mbX0, mbX1, mbC0, mbC1
#define SMEM_DYN (SMB + 48)
#define CTAS_PER_B 96

// ---- device scratch ----
__device__ float   g_ppart[B*4*36*16];
__device__ __align__(16) __half g_xh[(size_t)B*4*PPLANE*16];  // [b][cc][pg][ci16] swizzled
__device__ __align__(16) uint32_t g_fh[B*2*4*9*2*32*4];  // [b][nh][cc][tap][kh][n32][k8]
__device__ __align__(16) __half g_yh[(size_t)B*CO*PLANE]; // raw conv out, fp16
__device__ float   g_stats[B][GROUPS][2];
__device__ int     g_done[B];

__device__ __forceinline__ void mma16(float* c, const uint32_t* a, const uint32_t* b) {
    asm volatile(
        "mma.sync.aligned.m16n8k16.row.col.f32.f16.f16.f32 "
        "{%0,%1,%2,%3}, {%4,%5,%6,%7}, {%8,%9}, {%0,%1,%2,%3};"
        : "+f"(c[0]), "+f"(c[1]), "+f"(c[2]), "+f"(c[3])
        : "r"(a[0]), "r"(a[1]), "r"(a[2]), "r"(a[3]), "r"(b[0]), "r"(b[1]));
}
__device__ __forceinline__ void ldsm4(uint32_t* r, uint32_t addr) {
    asm volatile("ldmatrix.sync.aligned.m8n8.x4.shared.b16 {%0,%1,%2,%3}, [%4];"
                 : "=r"(r[0]), "=r"(r[1]), "=r"(r[2]), "=r"(r[3]) : "r"(addr));
}
__device__ __forceinline__ void bulk_cp(uint32_t dst, const void* src,
                                        uint32_t bytes, uint32_t mbar) {
    asm volatile(
        "cp.async.bulk.shared::cluster.global.mbarrier::complete_tx::bytes "
        "[%0], [%1], %2, [%3];"
        :: "r"(dst), "l"(src), "r"(bytes), "r"(mbar) : "memory");
}
__device__ __forceinline__ void mbar_init(uint32_t a, uint32_t c) {
    asm volatile("mbarrier.init.shared.b64 [%0], %1;" :: "r"(a), "r"(c) : "memory");
}
__device__ __forceinline__ void mbar_expect(uint32_t a, uint32_t bytes) {
    asm volatile("mbarrier.arrive.expect_tx.shared.b64 _, [%0], %1;"
                 :: "r"(a), "r"(bytes) : "memory");
}
__device__ __forceinline__ void mbar_arrive(uint32_t a) {
    asm volatile("mbarrier.arrive.shared.b64 _, [%0];" :: "r"(a) : "memory");
}
__device__ __forceinline__ void mbar_wait(uint32_t a, uint32_t par) {
    asm volatile("{\n\t.reg .pred P;\n"
                 "WAIT_%=:\n\t"
                 "mbarrier.try_wait.parity.acquire.cta.shared::cta.b64 P, [%0], %1;\n\t"
                 "@!P bra WAIT_%=;\n\t}" :: "r"(a), "r"(par) : "memory");
}

// ============================================================
// K1: convert x -> padded swizzled fp16 [b][cc][pg][ci16] + pool partials
// ============================================================
__global__ void __launch_bounds__(256)
convert_pool_kernel(const float* __restrict__ x) {
    int b = blockIdx.z, cc = blockIdx.y, pb = blockIdx.x;
    int t = threadIdx.x;
    const float* xp = x + ((size_t)b*CI + cc*16)*PLANE + pb*1024;
    __half* outbase = g_xh + (size_t)(b*4+cc)*PPLANE*16;

    float s[16];
    #pragma unroll
    for (int i = 0; i < 16; i++) s[i] = 0.f;

    #pragma unroll
    for (int it = 0; it < 4; it++) {
        int p = it*256 + t;
        int pp = pb*1024 + p;
        int gy = pp / WW, gx = pp - gy*WW;
        int pg = (gy+1)*WP + gx + 4;
        uint32_t h2[8];
        #pragma unroll
        for (int ci = 0; ci < 16; ci += 2) {
            float v0 = xp[(size_t)ci*PLANE + p];
            float v1 = xp[(size_t)(ci+1)*PLANE + p];
            s[ci] += v0; s[ci+1] += v1;
            __half2 h = __floats2half2_rn(v0, v1);
            h2[ci>>1] = *(uint32_t*)&h;
        }
        int sw = (pg >> 2) & 1;
        uint4* o = (uint4*)(outbase + (size_t)pg*16);
        o[0 ^ sw] = make_uint4(h2[0], h2[1], h2[2], h2[3]);
        o[1 ^ sw] = make_uint4(h2[4], h2[5], h2[6], h2[7]);
    }
    __shared__ float red[8][16];
    #pragma unroll
    for (int o = 16; o > 0; o >>= 1)
        #pragma unroll
        for (int i = 0; i < 16; i++) s[i] += __shfl_down_sync(~0u, s[i], o);
    if ((t & 31) == 0)
        #pragma unroll
        for (int i = 0; i < 16; i++) red[t>>5][i] = s[i];
    __syncthreads();
    if (t < 16) {
        float tot = 0.f;
        #pragma unroll
        for (int w = 0; w < 8; w++) tot += red[w][t];
        g_ppart[(((b*4+cc)*36) + pb)*16 + t] = tot;
    }
}

// ============================================================
// K2: fused attention + filter synthesis; block 0 zeroes stats+done.
// ============================================================
__global__ void __launch_bounds__(256)
filt_kernel(const float* __restrict__ W,
            const float* __restrict__ w1,
            const float* __restrict__ w2,
            const float* __restrict__ b2) {
    __shared__ float sp[CI];
    __shared__ float sh[HID];
    __shared__ float sa[KDY];

    int t = threadIdx.x;
    int idx = blockIdx.x * 256 + t;
    int b = blockIdx.x / 72;

    if (blockIdx.x == 0) {
        ((float*)g_stats)[t] = 0.f;
        if (t < B) g_done[t] = 0;
    }

    if (t < 64) {
        int cc = t >> 4, i = t & 15;
        float a = 0.f;
        const float* pp = g_ppart + ((b*4+cc)*36)*16 + i;
        #pragma unroll 4
        for (int p = 0; p < 36; p++) a += pp[p*16];
        sp[t] = a / (float)PLANE;
    }
    __syncthreads();
    if (t < HID) {
        float a = 0.f;
        #pragma unroll 8
        for (int c = 0; c < CI; c++) a += sp[c] * w1[t*CI + c];
        sh[t] = a > 0.f ? a : 0.f;
    }
    __syncthreads();
    if (t < KDY) {
        float a = b2[t];
        #pragma unroll
        for (int j = 0; j < HID; j++) a += sh[j] * w2[t*HID + j];
        sa[t] = a / TEMPERATURE;
    }
    __syncthreads();
    if (t == 0) {
        float m = fmaxf(fmaxf(sa[0], sa[1]), fmaxf(sa[2], sa[3]));
        float e0 = expf(sa[0]-m), e1 = expf(sa[1]-m),
              e2 = expf(sa[2]-m), e3 = expf(sa[3]-m);
        float inv = 1.f / (e0+e1+e2+e3);
        sa[0] = e0*inv; sa[1] = e1*inv; sa[2] = e2*inv; sa[3] = e3*inv;
    }
    __syncthreads();

    int k2  = idx & 3;
    int n   = (idx >> 2) & 31;
    int kh  = (idx >> 7) & 1;
    int t2  = idx >> 8;
    int tap = t2 % 9;
    int t3  = t2 / 9;
    int cc  = t3 & 3;
    int nh  = (t3 >> 2) & 1;
    int ng  = nh*32 + n;
    int ci0 = cc*16 + kh*8 + 2*k2;
    const int ks = CO*CI*9;
    float a0 = sa[0], a1 = sa[1], a2 = sa[2], a3 = sa[3];
    int w0 = (ng*CI + ci0)*9 + tap;
    int w1i = w0 + 9;
    float f0 = a0*W[w0]  + a1*W[w0+ks]  + a2*W[w0+2*ks]  + a3*W[w0+3*ks];
    float f1 = a0*W[w1i] + a1*W[w1i+ks] + a2*W[w1i+2*ks] + a3*W[w1i+3*ks];
    __half2 h = __floats2half2_rn(f0, f1);
    g_fh[idx] = *(uint32_t*)&h;
}

// ============================================================
// K3: implicit-GEMM fp16 conv + FUSED GroupNorm epilogue.
// Conv phase identical to R14. After stats, per-sample arrival
// counter; the 96 CTAs of b then cooperatively normalize b while
// later samples' conv overlaps.
// ============================================================
__global__ void __launch_bounds__(256, 3)
conv_kernel(float* __restrict__ out,
            const float* __restrict__ gamma,
            const float* __restrict__ beta) {
    extern __shared__ __align__(128) unsigned char dynsm[];
    __shared__ float sga[CO], sbe[CO];
    const uint32_t smb = (uint32_t)__cvta_generic_to_shared(dynsm);
    const uint32_t mbF = smb + SMB;
    const uint32_t mbX = smb + SMB + 8;    // [2]
    const uint32_t mbC = smb + SMB + 24;   // [2], count 8

    const int tid = threadIdx.x;
    const int w = tid >> 5, lane = tid & 31;
    const int tig = lane & 3, grp = lane >> 2;
    const int row_w = w >> 1, col32 = (w & 1) * 32;
    const int b  = blockIdx.z;
    const int nh = blockIdx.y;
    const int y0 = blockIdx.x * 4;

    const int pixoff  = ((lane >> 3) & 1) * 8 + (lane & 7);
    const int halfbit = (lane >> 4) & 1;
    const uint32_t blane = (((lane >> 3) & 1) << 9) +
                           (((lane >> 4) & 1)*8 + (lane & 7)) * 16;

    float acc[2][4][4];
    float s[4], q[4];
    #pragma unroll
    for (int g = 0; g < 4; g++) { s[g] = 0.f; q[g] = 0.f; }

    if (tid == 0) {
        mbar_init(mbF, 1);
        mbar_init(mbX, 1);     mbar_init(mbX + 8, 1);
        mbar_init(mbC, 8);     mbar_init(mbC + 8, 8);
    }
    __syncthreads();

    auto stage_x = [&](int step, int buf) {   // single-thread
        int t = step >> 2, cc = step & 3;
        uint32_t bar = mbX + buf*8;
        mbar_expect(bar, SXHB);
        const __half* xs = g_xh +
            ((size_t)(b*4+cc)*PPLANE + (size_t)y0*WP + t*64)*16;
        #pragma unroll
        for (int r = 0; r < 6; r++)
            bulk_cp(smb + SX0 + buf*SXHB + r*2304, xs + (size_t)r*WP*16, 2304, bar);
    };

    if (tid == 0) {
        mbar_expect(mbF, SFB);
        const uint32_t* fsrc = g_fh + (size_t)(b*2+nh)*9216;
        #pragma unroll
        for (int cc = 0; cc < 4; cc++)
            bulk_cp(smb + cc*9216, fsrc + cc*2304, 9216, mbF);
        stage_x(0, 0);
        stage_x(1, 1);       // depth-2 prefetch
    }
    mbar_wait(mbF, 0);

    for (int step = 0; step < NSTEP; step++) {
        const int cc = step & 3, tile = step >> 2, buf = step & 1;
        const int ph = (step >> 1) & 1;
        if (cc == 0) {
            #pragma unroll
            for (int mt = 0; mt < 2; mt++)
                #pragma unroll
                for (int nt = 0; nt < 4; nt++)
                    #pragma unroll
                    for (int r = 0; r < 4; r++) acc[mt][nt][r] = 0.f;
        }
        mbar_wait(mbX + buf*8, ph);

        // ---- compute chunk ----
        {
            const uint32_t sxa = smb + SX0 + buf*SXHB;
            const uint32_t sba = smb + cc*9216 + blane;
            #pragma unroll
            for (int tap = 0; tap < 9; tap++) {
                const int tg = tap / 3, tloc = tap - tg*3;
                const int P = (row_w + tg)*72 + col32 + 3 + tloc + pixoff;
                uint32_t a[2][4];
                #pragma unroll
                for (int mt = 0; mt < 2; mt++) {
                    int pix = P + mt*16;
                    ldsm4(a[mt], sxa + pix*32 + (((halfbit ^ (pix >> 2)) & 1) << 4));
                }
                uint32_t bfr[8];
                ldsm4(bfr,     sba + tap*1024);
                ldsm4(bfr + 4, sba + tap*1024 + 256);
                #pragma unroll
                for (int mt = 0; mt < 2; mt++)
                    #pragma unroll
                    for (int nt = 0; nt < 4; nt++)
                        mma16(acc[mt][nt], a[mt], &bfr[nt*2]);
            }
        }

        if (lane == 0) mbar_arrive(mbC + buf*8);

        if (cc == 3) {   // tile epilogue: fp16 raw y + GN partials
            __half* ob = g_yh + (size_t)b*CO*PLANE + (y0 + row_w)*WW;
            const int x0 = tile*64;
            #pragma unroll
            for (int mt = 0; mt < 2; mt++) {
                #pragma unroll
                for (int nt = 0; nt < 4; nt++) {
                    #pragma unroll
                    for (int r = 0; r < 4; r++) {
                        float v = acc[mt][nt][r];
                        int gx = x0 + col32 + mt*16 + grp + ((r >> 1) << 3);
                        int co = nh*32 + nt*8 + tig*2 + (r & 1);
                        ob[co*PLANE + gx] = __float2half_rn(v);
                        s[nt] += v;
                        q[nt] += v*v;
                    }
                }
            }
        }

        if (tid == 0 && step + 2 < NSTEP) {
            mbar_wait(mbC + buf*8, ph);
            stage_x(step + 2, buf);
        }
    }

    // ---- GN partial reduction ----
    #pragma unroll
    for (int o = 16; o > 0; o >>= 1) {
        #pragma unroll
        for (int g = 0; g < 4; g++) {
            s[g] += __shfl_down_sync(~0u, s[g], o);
            q[g] += __shfl_down_sync(~0u, q[g], o);
        }
    }
    if (lane == 0) {
        #pragma unroll
        for (int g = 0; g < 4; g++) {
            atomicAdd(&g_stats[b][nh*4 + g][0], s[g]);
            atomicAdd(&g_stats[b][nh*4 + g][1], q[g]);
        }
        __threadfence();     // publish stats + y before arrival
    }
    __syncthreads();

    // ---- per-sample arrival + spin (96 CTAs per b, contiguous) ----
    if (tid == 0) {
        atomicAdd(&g_done[b], 1);
        volatile int* vd = (volatile int*)g_done;
        while (vd[b] < CTAS_PER_B) { }
        __threadfence();
    }
    __syncthreads();

    // ---- fused norm phase: this CTA's 1/96 share of sample b ----
    if (tid < CO) {
        int g = tid >> 3;
        float ss = g_stats[b][g][0], qq = g_stats[b][g][1];
        const float invN = 1.f / (float)(CPG * PLANE);
        float mean = ss * invN;
        float var  = qq * invN - mean*mean;
        float rstd = rsqrtf(var + EPS);
        float gsc = gamma[tid] * rstd;
        sga[tid] = gsc;
        sbe[tid] = beta[tid] - mean*gsc;
    }
    __syncthreads();

    const int cid = blockIdx.y*48 + blockIdx.x;   // 0..95
    #pragma unroll
    for (int it = 0; it < 12; it++) {
        int u  = cid*3072 + it*256 + tid;         // 8-px unit within sample
        int co = u / (PLANE/8);
        int r  = u - co*(PLANE/8);
        float ga = sga[co], be = sbe[co];
        size_t clin = (size_t)b*CO + co;
        uint4 v = ((const uint4*)(g_yh + clin*PLANE))[r];
        const uint32_t* pv = (const uint32_t*)&v;
        float4 o0, o1;
        __half2 h0 = *(const __half2*)&pv[0];
        __half2 h1 = *(const __half2*)&pv[1];
        __half2 h2 = *(const __half2*)&pv[2];
        __half2 h3 = *(const __half2*)&pv[3];
        float2 f0 = __half22float2(h0), f1 = __half22float2(h1);
        float2 f2 = __half22float2(h2), f3 = __half22float2(h3);
        float y;
        y = f0.x*ga + be; o0.x = y >= 0.f ? y : SLOPE*y;
        y = f0.y*ga + be; o0.y = y >= 0.f ? y : SLOPE*y;
        y = f1.x*ga + be; o0.z = y >= 0.f ? y : SLOPE*y;
        y = f1.y*ga + be; o0.w = y >= 0.f ? y : SLOPE*y;
        y = f2.x*ga + be; o1.x = y >= 0.f ? y : SLOPE*y;
        y = f2.y*ga + be; o1.y = y >= 0.f ? y : SLOPE*y;
        y = f3.x*ga + be; o1.z = y >= 0.f ? y : SLOPE*y;
        y = f3.y*ga + be; o1.w = y >= 0.f ? y : SLOPE*y;
        float4* op = (float4*)(out + clin*PLANE) + r*2;
        op[0] = o0;
        op[1] = o1;
    }
}

// ============================================================
extern "C" void kernel_launch(void* const* d_in, const int* in_sizes, int n_in,
                              void* d_out, int out_size) {
    const float* x  = (const float*)d_in[0];
    const float* w1 = (const float*)d_in[1];
    const float* w2 = (const float*)d_in[2];
    const float* b2 = (const float*)d_in[3];
    const float* W  = (const float*)d_in[4];
    const float* ga = (const float*)d_in[5];
    const float* be = (const float*)d_in[6];
    float* out = (float*)d_out;

    cudaFuncSetAttribute(conv_kernel,
                         cudaFuncAttributeMaxDynamicSharedMemorySize, SMEM_DYN);

    convert_pool_kernel<<<dim3(36, 4, B), 256>>>(x);
    filt_kernel<<<(B*2*4*9*2*32*4)/256, 256>>>(W, w1, w2, b2);
    conv_kernel<<<dim3(48, 2, B), 256, SMEM_DYN>>>(out, ga, be);
}

// round 16
// speedup vs baseline: 1.0912x; 1.0912x over previous
#include <cuda_runtime.h>
#include <cuda_fp16.h>
#include <cstdint>

#define B 16
#define CI 64
#define CO 64
#define HH 192
#define WW 192
#define KDY 4
#define HID 17
#define GROUPS 8
#define CPG 8
#define PLANE (HH*WW)
#define TEMPERATURE 30.0f
#define EPS 1e-5f
#define SLOPE 0.01f

// padded fp16 x: rows 0..193 (=gy+1), cols 0..199 (=gx+4), halo zero
#define WP 200
#define HP 194
#define PPLANE (HP*WP)

// conv: 4 ci-chunks, 3 col tiles, filters resident per (b, n-half)
#define NCH 4
#define NTILE 3
#define NSTEP (NCH*NTILE)
#define SFB 36864                   // filters: 4cc*9tap*2kh*32n*16B
#define SXHB 13824                  // x tile: 6 rows * 72 px * 32B
#define SX0 SFB
#define SMB (SFB + 2*SXHB)          // mbF, mbX0, mbX1, mbC0, mbC1
#define SMEM_DYN (SMB + 48)

// ---- device scratch ----
__device__ float   g_ppart[B*4*36*16];
__device__ __align__(16) __half g_xh[(size_t)B*4*PPLANE*16];  // [b][cc][pg][ci16] swizzled
__device__ __align__(16) uint32_t g_fh[B*2*4*9*2*32*4];  // [b][nh][cc][tap][kh][n32][k8]
__device__ __align__(16) __half g_yh[(size_t)B*CO*PLANE]; // raw conv out, fp16
__device__ float   g_stats[B][GROUPS][2];

__device__ __forceinline__ void mma16(float* c, const uint32_t* a, const uint32_t* b) {
    asm volatile(
        "mma.sync.aligned.m16n8k16.row.col.f32.f16.f16.f32 "
        "{%0,%1,%2,%3}, {%4,%5,%6,%7}, {%8,%9}, {%0,%1,%2,%3};"
        : "+f"(c[0]), "+f"(c[1]), "+f"(c[2]), "+f"(c[3])
        : "r"(a[0]), "r"(a[1]), "r"(a[2]), "r"(a[3]), "r"(b[0]), "r"(b[1]));
}
__device__ __forceinline__ void ldsm4(uint32_t* r, uint32_t addr) {
    asm volatile("ldmatrix.sync.aligned.m8n8.x4.shared.b16 {%0,%1,%2,%3}, [%4];"
                 : "=r"(r[0]), "=r"(r[1]), "=r"(r[2]), "=r"(r[3]) : "r"(addr));
}
__device__ __forceinline__ void bulk_cp(uint32_t dst, const void* src,
                                        uint32_t bytes, uint32_t mbar) {
    asm volatile(
        "cp.async.bulk.shared::cluster.global.mbarrier::complete_tx::bytes "
        "[%0], [%1], %2, [%3];"
        :: "r"(dst), "l"(src), "r"(bytes), "r"(mbar) : "memory");
}
__device__ __forceinline__ void mbar_init(uint32_t a, uint32_t c) {
    asm volatile("mbarrier.init.shared.b64 [%0], %1;" :: "r"(a), "r"(c) : "memory");
}
__device__ __forceinline__ void mbar_expect(uint32_t a, uint32_t bytes) {
    asm volatile("mbarrier.arrive.expect_tx.shared.b64 _, [%0], %1;"
                 :: "r"(a), "r"(bytes) : "memory");
}
__device__ __forceinline__ void mbar_arrive(uint32_t a) {
    asm volatile("mbarrier.arrive.shared.b64 _, [%0];" :: "r"(a) : "memory");
}
__device__ __forceinline__ void mbar_wait(uint32_t a, uint32_t par) {
    asm volatile("{\n\t.reg .pred P;\n"
                 "WAIT_%=:\n\t"
                 "mbarrier.try_wait.parity.acquire.cta.shared::cta.b64 P, [%0], %1;\n\t"
                 "@!P bra WAIT_%=;\n\t}" :: "r"(a), "r"(par) : "memory");
}

// ============================================================
// K1: convert x -> padded swizzled fp16 [b][cc][pg][ci16] + pool partials
// ============================================================
__global__ void __launch_bounds__(256)
convert_pool_kernel(const float* __restrict__ x) {
    int b = blockIdx.z, cc = blockIdx.y, pb = blockIdx.x;
    int t = threadIdx.x;
    const float* xp = x + ((size_t)b*CI + cc*16)*PLANE + pb*1024;
    __half* outbase = g_xh + (size_t)(b*4+cc)*PPLANE*16;

    float s[16];
    #pragma unroll
    for (int i = 0; i < 16; i++) s[i] = 0.f;

    #pragma unroll
    for (int it = 0; it < 4; it++) {
        int p = it*256 + t;
        int pp = pb*1024 + p;
        int gy = pp / WW, gx = pp - gy*WW;
        int pg = (gy+1)*WP + gx + 4;
        uint32_t h2[8];
        #pragma unroll
        for (int ci = 0; ci < 16; ci += 2) {
            float v0 = xp[(size_t)ci*PLANE + p];
            float v1 = xp[(size_t)(ci+1)*PLANE + p];
            s[ci] += v0; s[ci+1] += v1;
            __half2 h = __floats2half2_rn(v0, v1);
            h2[ci>>1] = *(uint32_t*)&h;
        }
        int sw = (pg >> 2) & 1;
        uint4* o = (uint4*)(outbase + (size_t)pg*16);
        o[0 ^ sw] = make_uint4(h2[0], h2[1], h2[2], h2[3]);
        o[1 ^ sw] = make_uint4(h2[4], h2[5], h2[6], h2[7]);
    }
    __shared__ float red[8][16];
    #pragma unroll
    for (int o = 16; o > 0; o >>= 1)
        #pragma unroll
        for (int i = 0; i < 16; i++) s[i] += __shfl_down_sync(~0u, s[i], o);
    if ((t & 31) == 0)
        #pragma unroll
        for (int i = 0; i < 16; i++) red[t>>5][i] = s[i];
    __syncthreads();
    if (t < 16) {
        float tot = 0.f;
        #pragma unroll
        for (int w = 0; w < 8; w++) tot += red[w][t];
        g_ppart[(((b*4+cc)*36) + pb)*16 + t] = tot;
    }
}

// ============================================================
// K2: fused attention + filter synthesis; block 0 zeroes stats.
// ============================================================
__global__ void __launch_bounds__(256)
filt_kernel(const float* __restrict__ W,
            const float* __restrict__ w1,
            const float* __restrict__ w2,
            const float* __restrict__ b2) {
    __shared__ float sp[CI];
    __shared__ float sh[HID];
    __shared__ float sa[KDY];

    int t = threadIdx.x;
    int idx = blockIdx.x * 256 + t;
    int b = blockIdx.x / 72;

    if (blockIdx.x == 0) ((float*)g_stats)[t] = 0.f;

    if (t < 64) {
        int cc = t >> 4, i = t & 15;
        float a = 0.f;
        const float* pp = g_ppart + ((b*4+cc)*36)*16 + i;
        #pragma unroll 4
        for (int p = 0; p < 36; p++) a += pp[p*16];
        sp[t] = a / (float)PLANE;
    }
    __syncthreads();
    if (t < HID) {
        float a = 0.f;
        #pragma unroll 8
        for (int c = 0; c < CI; c++) a += sp[c] * w1[t*CI + c];
        sh[t] = a > 0.f ? a : 0.f;
    }
    __syncthreads();
    if (t < KDY) {
        float a = b2[t];
        #pragma unroll
        for (int j = 0; j < HID; j++) a += sh[j] * w2[t*HID + j];
        sa[t] = a / TEMPERATURE;
    }
    __syncthreads();
    if (t == 0) {
        float m = fmaxf(fmaxf(sa[0], sa[1]), fmaxf(sa[2], sa[3]));
        float e0 = expf(sa[0]-m), e1 = expf(sa[1]-m),
              e2 = expf(sa[2]-m), e3 = expf(sa[3]-m);
        float inv = 1.f / (e0+e1+e2+e3);
        sa[0] = e0*inv; sa[1] = e1*inv; sa[2] = e2*inv; sa[3] = e3*inv;
    }
    __syncthreads();

    int k2  = idx & 3;
    int n   = (idx >> 2) & 31;
    int kh  = (idx >> 7) & 1;
    int t2  = idx >> 8;
    int tap = t2 % 9;
    int t3  = t2 / 9;
    int cc  = t3 & 3;
    int nh  = (t3 >> 2) & 1;
    int ng  = nh*32 + n;
    int ci0 = cc*16 + kh*8 + 2*k2;
    const int ks = CO*CI*9;
    float a0 = sa[0], a1 = sa[1], a2 = sa[2], a3 = sa[3];
    int w0 = (ng*CI + ci0)*9 + tap;
    int w1i = w0 + 9;
    float f0 = a0*W[w0]  + a1*W[w0+ks]  + a2*W[w0+2*ks]  + a3*W[w0+3*ks];
    float f1 = a0*W[w1i] + a1*W[w1i+ks] + a2*W[w1i+2*ks] + a3*W[w1i+3*ks];
    __half2 h = __floats2half2_rn(f0, f1);
    g_fh[idx] = *(uint32_t*)&h;
}

// ============================================================
// K3: implicit-GEMM fp16 conv, filters RESIDENT in smem.
// Warp-decoupled pipeline; raw y written as fp16 to g_yh (L2-res).
// ============================================================
__global__ void __launch_bounds__(256, 3)
conv_kernel() {
    extern __shared__ __align__(128) unsigned char dynsm[];
    const uint32_t smb = (uint32_t)__cvta_generic_to_shared(dynsm);
    const uint32_t mbF = smb + SMB;
    const uint32_t mbX = smb + SMB + 8;    // [2]
    const uint32_t mbC = smb + SMB + 24;   // [2], count 8

    const int tid = threadIdx.x;
    const int w = tid >> 5, lane = tid & 31;
    const int tig = lane & 3, grp = lane >> 2;
    const int row_w = w >> 1, col32 = (w & 1) * 32;
    const int b  = blockIdx.z;
    const int nh = blockIdx.y;
    const int y0 = blockIdx.x * 4;

    const int pixoff  = ((lane >> 3) & 1) * 8 + (lane & 7);
    const int halfbit = (lane >> 4) & 1;
    const uint32_t blane = (((lane >> 3) & 1) << 9) +
                           (((lane >> 4) & 1)*8 + (lane & 7)) * 16;

    float acc[2][4][4];
    float s[4], q[4];
    #pragma unroll
    for (int g = 0; g < 4; g++) { s[g] = 0.f; q[g] = 0.f; }

    if (tid == 0) {
        mbar_init(mbF, 1);
        mbar_init(mbX, 1);     mbar_init(mbX + 8, 1);
        mbar_init(mbC, 8);     mbar_init(mbC + 8, 8);
    }
    __syncthreads();

    auto stage_x = [&](int step, int buf) {   // single-thread
        int t = step >> 2, cc = step & 3;
        uint32_t bar = mbX + buf*8;
        mbar_expect(bar, SXHB);
        const __half* xs = g_xh +
            ((size_t)(b*4+cc)*PPLANE + (size_t)y0*WP + t*64)*16;
        #pragma unroll
        for (int r = 0; r < 6; r++)
            bulk_cp(smb + SX0 + buf*SXHB + r*2304, xs + (size_t)r*WP*16, 2304, bar);
    };

    if (tid == 0) {
        mbar_expect(mbF, SFB);
        const uint32_t* fsrc = g_fh + (size_t)(b*2+nh)*9216;
        #pragma unroll
        for (int cc = 0; cc < 4; cc++)
            bulk_cp(smb + cc*9216, fsrc + cc*2304, 9216, mbF);
        stage_x(0, 0);
        stage_x(1, 1);       // depth-2 prefetch
    }
    mbar_wait(mbF, 0);

    for (int step = 0; step < NSTEP; step++) {
        const int cc = step & 3, tile = step >> 2, buf = step & 1;
        const int ph = (step >> 1) & 1;
        if (cc == 0) {
            #pragma unroll
            for (int mt = 0; mt < 2; mt++)
                #pragma unroll
                for (int nt = 0; nt < 4; nt++)
                    #pragma unroll
                    for (int r = 0; r < 4; r++) acc[mt][nt][r] = 0.f;
        }
        mbar_wait(mbX + buf*8, ph);

        // ---- compute chunk ----
        {
            const uint32_t sxa = smb + SX0 + buf*SXHB;
            const uint32_t sba = smb + cc*9216 + blane;
            #pragma unroll
            for (int tap = 0; tap < 9; tap++) {
                const int tg = tap / 3, tloc = tap - tg*3;
                const int P = (row_w + tg)*72 + col32 + 3 + tloc + pixoff;
                uint32_t a[2][4];
                #pragma unroll
                for (int mt = 0; mt < 2; mt++) {
                    int pix = P + mt*16;
                    ldsm4(a[mt], sxa + pix*32 + (((halfbit ^ (pix >> 2)) & 1) << 4));
                }
                uint32_t bfr[8];
                ldsm4(bfr,     sba + tap*1024);
                ldsm4(bfr + 4, sba + tap*1024 + 256);
                #pragma unroll
                for (int mt = 0; mt < 2; mt++)
                    #pragma unroll
                    for (int nt = 0; nt < 4; nt++)
                        mma16(acc[mt][nt], a[mt], &bfr[nt*2]);
            }
        }

        // done reading this buffer: consumer arrive (one lane per warp)
        if (lane == 0) mbar_arrive(mbC + buf*8);

        if (cc == 3) {   // tile epilogue: fp16 raw y + GN partials
            __half* ob = g_yh + (size_t)b*CO*PLANE + (y0 + row_w)*WW;
            const int x0 = tile*64;
            #pragma unroll
            for (int mt = 0; mt < 2; mt++) {
                #pragma unroll
                for (int nt = 0; nt < 4; nt++) {
                    #pragma unroll
                    for (int r = 0; r < 4; r++) {
                        float v = acc[mt][nt][r];
                        int gx = x0 + col32 + mt*16 + grp + ((r >> 1) << 3);
                        int co = nh*32 + nt*8 + tig*2 + (r & 1);
                        ob[co*PLANE + gx] = __float2half_rn(v);
                        s[nt] += v;
                        q[nt] += v*v;
                    }
                }
            }
        }

        // producer: once all 8 warps released this buffer, restage it
        if (tid == 0 && step + 2 < NSTEP) {
            mbar_wait(mbC + buf*8, ph);
            stage_x(step + 2, buf);
        }
    }

    // ---- GN partial reduction (once, over all 3 tiles) ----
    #pragma unroll
    for (int o = 16; o > 0; o >>= 1) {
        #pragma unroll
        for (int g = 0; g < 4; g++) {
            s[g] += __shfl_down_sync(~0u, s[g], o);
            q[g] += __shfl_down_sync(~0u, q[g], o);
        }
    }
    if (lane == 0) {
        #pragma unroll
        for (int g = 0; g < 4; g++) {
            atomicAdd(&g_stats[b][nh*4 + g][0], s[g]);
            atomicAdd(&g_stats[b][nh*4 + g][1], q[g]);
        }
    }
}

// ============================================================
// K4: GroupNorm + affine + LeakyReLU, fp16 in -> fp32 out.
// 4 independent uint4 loads per thread (MLP=4) for DRAM saturation.
// ============================================================
__global__ void __launch_bounds__(256)
norm_kernel(float* __restrict__ out,
            const float* __restrict__ gamma,
            const float* __restrict__ beta) {
    const int PL8 = PLANE / 8;      // 4608 8-px units per (b,co)
    int base = blockIdx.x * 1024 + threadIdx.x;

    uint4 v[4];
    int clin[4], r[4];
    #pragma unroll
    for (int i = 0; i < 4; i++) {
        int u = base + i*256;
        int c = u / PL8;
        clin[i] = c;
        r[i] = u - c*PL8;
        v[i] = ((const uint4*)(g_yh + (size_t)c*PLANE))[r[i]];
    }

    #pragma unroll
    for (int i = 0; i < 4; i++) {
        int co = clin[i] & 63;
        int b  = clin[i] >> 6;
        int g  = co >> 3;
        float ss = g_stats[b][g][0], qq = g_stats[b][g][1];
        const float invN = 1.f / (float)(CPG * PLANE);
        float mean = ss * invN;
        float var  = qq * invN - mean*mean;
        float rstd = rsqrtf(var + EPS);
        float ga = gamma[co] * rstd;
        float be = beta[co] - mean*ga;

        const uint32_t* pv = (const uint32_t*)&v[i];
        float4 o0, o1;
        __half2 h0 = *(const __half2*)&pv[0];
        __half2 h1 = *(const __half2*)&pv[1];
        __half2 h2 = *(const __half2*)&pv[2];
        __half2 h3 = *(const __half2*)&pv[3];
        float2 f0 = __half22float2(h0), f1 = __half22float2(h1);
        float2 f2 = __half22float2(h2), f3 = __half22float2(h3);
        float y;
        y = f0.x*ga + be; o0.x = y >= 0.f ? y : SLOPE*y;
        y = f0.y*ga + be; o0.y = y >= 0.f ? y : SLOPE*y;
        y = f1.x*ga + be; o0.z = y >= 0.f ? y : SLOPE*y;
        y = f1.y*ga + be; o0.w = y >= 0.f ? y : SLOPE*y;
        y = f2.x*ga + be; o1.x = y >= 0.f ? y : SLOPE*y;
        y = f2.y*ga + be; o1.y = y >= 0.f ? y : SLOPE*y;
        y = f3.x*ga + be; o1.z = y >= 0.f ? y : SLOPE*y;
        y = f3.y*ga + be; o1.w = y >= 0.f ? y : SLOPE*y;
        float4* op = (float4*)(out + (size_t)clin[i]*PLANE) + r[i]*2;
        op[0] = o0;
        op[1] = o1;
    }
}

// ============================================================
extern "C" void kernel_launch(void* const* d_in, const int* in_sizes, int n_in,
                              void* d_out, int out_size) {
    const float* x  = (const float*)d_in[0];
    const float* w1 = (const float*)d_in[1];
    const float* w2 = (const float*)d_in[2];
    const float* b2 = (const float*)d_in[3];
    const float* W  = (const float*)d_in[4];
    const float* ga = (const float*)d_in[5];
    const float* be = (const float*)d_in[6];
    float* out = (float*)d_out;

    cudaFuncSetAttribute(conv_kernel,
                         cudaFuncAttributeMaxDynamicSharedMemorySize, SMEM_DYN);

    convert_pool_kernel<<<dim3(36, 4, B), 256>>>(x);
    filt_kernel<<<(B*2*4*9*2*32*4)/256, 256>>>(W, w1, w2, b2);
    conv_kernel<<<dim3(48, 2, B), 256, SMEM_DYN>>>();
    norm_kernel<<<(B*CO*PLANE/8/4)/256, 256>>>(out, ga, be);
}

// round 17
// speedup vs baseline: 1.1142x; 1.0211x over previous
#include <cuda_runtime.h>
#include <cuda_fp16.h>
#include <cstdint>

#define B 16
#define CI 64
#define CO 64
#define HH 192
#define WW 192
#define KDY 4
#define HID 17
#define GROUPS 8
#define CPG 8
#define PLANE (HH*WW)
#define TEMPERATURE 30.0f
#define EPS 1e-5f
#define SLOPE 0.01f

// padded fp16 x: rows 0..193 (=gy+1), cols 0..199 (=gx+4), halo zero
#define WP 200
#define HP 194
#define PPLANE (HP*WP)

// conv: 4 ci-chunks, 3 col tiles, FULL filter set resident (64 co)
#define NCH 4
#define NTILE 3
#define NSTEP (NCH*NTILE)
#define SFB 73728                   // filters: 4cc*9tap*2kh*64n*16B
#define SXHB 13824                  // x tile: 6 rows * 72 px * 32B
#define SX0 SFB
#define SMB (SFB + 2*SXHB)          // 101376: mbF, mbX0, mbX1, mbC0, mbC1
#define SMEM_DYN (SMB + 48)

// ---- device scratch ----
__device__ float   g_ppart[B*4*36*16];
__device__ __align__(16) __half g_xh[(size_t)B*4*PPLANE*16];  // [b][cc][pg][ci16] swizzled
__device__ __align__(16) uint32_t g_fh[B*4*9*2*64*4];  // [b][cc][tap][kh][n64][k8]
__device__ __align__(16) __half g_yh[(size_t)B*CO*PLANE]; // raw conv out, fp16
__device__ float   g_stats[B][GROUPS][2];

__device__ __forceinline__ void mma16(float* c, const uint32_t* a, const uint32_t* b) {
    asm volatile(
        "mma.sync.aligned.m16n8k16.row.col.f32.f16.f16.f32 "
        "{%0,%1,%2,%3}, {%4,%5,%6,%7}, {%8,%9}, {%0,%1,%2,%3};"
        : "+f"(c[0]), "+f"(c[1]), "+f"(c[2]), "+f"(c[3])
        : "r"(a[0]), "r"(a[1]), "r"(a[2]), "r"(a[3]), "r"(b[0]), "r"(b[1]));
}
__device__ __forceinline__ void ldsm4(uint32_t* r, uint32_t addr) {
    asm volatile("ldmatrix.sync.aligned.m8n8.x4.shared.b16 {%0,%1,%2,%3}, [%4];"
                 : "=r"(r[0]), "=r"(r[1]), "=r"(r[2]), "=r"(r[3]) : "r"(addr));
}
__device__ __forceinline__ void bulk_cp(uint32_t dst, const void* src,
                                        uint32_t bytes, uint32_t mbar) {
    asm volatile(
        "cp.async.bulk.shared::cluster.global.mbarrier::complete_tx::bytes "
        "[%0], [%1], %2, [%3];"
        :: "r"(dst), "l"(src), "r"(bytes), "r"(mbar) : "memory");
}
__device__ __forceinline__ void mbar_init(uint32_t a, uint32_t c) {
    asm volatile("mbarrier.init.shared.b64 [%0], %1;" :: "r"(a), "r"(c) : "memory");
}
__device__ __forceinline__ void mbar_expect(uint32_t a, uint32_t bytes) {
    asm volatile("mbarrier.arrive.expect_tx.shared.b64 _, [%0], %1;"
                 :: "r"(a), "r"(bytes) : "memory");
}
__device__ __forceinline__ void mbar_arrive(uint32_t a) {
    asm volatile("mbarrier.arrive.shared.b64 _, [%0];" :: "r"(a) : "memory");
}
__device__ __forceinline__ void mbar_wait(uint32_t a, uint32_t par) {
    asm volatile("{\n\t.reg .pred P;\n"
                 "WAIT_%=:\n\t"
                 "mbarrier.try_wait.parity.acquire.cta.shared::cta.b64 P, [%0], %1;\n\t"
                 "@!P bra WAIT_%=;\n\t}" :: "r"(a), "r"(par) : "memory");
}

// ============================================================
// K1: convert x -> padded swizzled fp16 [b][cc][pg][ci16] + pool partials
// ============================================================
__global__ void __launch_bounds__(256)
convert_pool_kernel(const float* __restrict__ x) {
    int b = blockIdx.z, cc = blockIdx.y, pb = blockIdx.x;
    int t = threadIdx.x;
    const float* xp = x + ((size_t)b*CI + cc*16)*PLANE + pb*1024;
    __half* outbase = g_xh + (size_t)(b*4+cc)*PPLANE*16;

    float s[16];
    #pragma unroll
    for (int i = 0; i < 16; i++) s[i] = 0.f;

    #pragma unroll
    for (int it = 0; it < 4; it++) {
        int p = it*256 + t;
        int pp = pb*1024 + p;
        int gy = pp / WW, gx = pp - gy*WW;
        int pg = (gy+1)*WP + gx + 4;
        uint32_t h2[8];
        #pragma unroll
        for (int ci = 0; ci < 16; ci += 2) {
            float v0 = xp[(size_t)ci*PLANE + p];
            float v1 = xp[(size_t)(ci+1)*PLANE + p];
            s[ci] += v0; s[ci+1] += v1;
            __half2 h = __floats2half2_rn(v0, v1);
            h2[ci>>1] = *(uint32_t*)&h;
        }
        int sw = (pg >> 2) & 1;
        uint4* o = (uint4*)(outbase + (size_t)pg*16);
        o[0 ^ sw] = make_uint4(h2[0], h2[1], h2[2], h2[3]);
        o[1 ^ sw] = make_uint4(h2[4], h2[5], h2[6], h2[7]);
    }
    __shared__ float red[8][16];
    #pragma unroll
    for (int o = 16; o > 0; o >>= 1)
        #pragma unroll
        for (int i = 0; i < 16; i++) s[i] += __shfl_down_sync(~0u, s[i], o);
    if ((t & 31) == 0)
        #pragma unroll
        for (int i = 0; i < 16; i++) red[t>>5][i] = s[i];
    __syncthreads();
    if (t < 16) {
        float tot = 0.f;
        #pragma unroll
        for (int w = 0; w < 8; w++) tot += red[w][t];
        g_ppart[(((b*4+cc)*36) + pb)*16 + t] = tot;
    }
}

// ============================================================
// K2: fused attention + filter synthesis; block 0 zeroes stats.
// Output layout: [b][cc][tap][kh][n64][k8]
// ============================================================
__global__ void __launch_bounds__(256)
filt_kernel(const float* __restrict__ W,
            const float* __restrict__ w1,
            const float* __restrict__ w2,
            const float* __restrict__ b2) {
    __shared__ float sp[CI];
    __shared__ float sh[HID];
    __shared__ float sa[KDY];

    int t = threadIdx.x;
    int idx = blockIdx.x * 256 + t;
    int b = blockIdx.x / 72;

    if (blockIdx.x == 0) ((float*)g_stats)[t] = 0.f;

    if (t < 64) {
        int cc = t >> 4, i = t & 15;
        float a = 0.f;
        const float* pp = g_ppart + ((b*4+cc)*36)*16 + i;
        #pragma unroll 4
        for (int p = 0; p < 36; p++) a += pp[p*16];
        sp[t] = a / (float)PLANE;
    }
    __syncthreads();
    if (t < HID) {
        float a = 0.f;
        #pragma unroll 8
        for (int c = 0; c < CI; c++) a += sp[c] * w1[t*CI + c];
        sh[t] = a > 0.f ? a : 0.f;
    }
    __syncthreads();
    if (t < KDY) {
        float a = b2[t];
        #pragma unroll
        for (int j = 0; j < HID; j++) a += sh[j] * w2[t*HID + j];
        sa[t] = a / TEMPERATURE;
    }
    __syncthreads();
    if (t == 0) {
        float m = fmaxf(fmaxf(sa[0], sa[1]), fmaxf(sa[2], sa[3]));
        float e0 = expf(sa[0]-m), e1 = expf(sa[1]-m),
              e2 = expf(sa[2]-m), e3 = expf(sa[3]-m);
        float inv = 1.f / (e0+e1+e2+e3);
        sa[0] = e0*inv; sa[1] = e1*inv; sa[2] = e2*inv; sa[3] = e3*inv;
    }
    __syncthreads();

    int k2  = idx & 3;
    int n   = (idx >> 2) & 63;
    int kh  = (idx >> 8) & 1;
    int t2  = idx >> 9;
    int tap = t2 % 9;
    int t3  = t2 / 9;
    int cc  = t3 & 3;
    int ci0 = cc*16 + kh*8 + 2*k2;
    const int ks = CO*CI*9;
    float a0 = sa[0], a1 = sa[1], a2 = sa[2], a3 = sa[3];
    int w0 = (n*CI + ci0)*9 + tap;
    int w1i = w0 + 9;
    float f0 = a0*W[w0]  + a1*W[w0+ks]  + a2*W[w0+2*ks]  + a3*W[w0+3*ks];
    float f1 = a0*W[w1i] + a1*W[w1i+ks] + a2*W[w1i+2*ks] + a3*W[w1i+3*ks];
    __half2 h = __floats2half2_rn(f0, f1);
    g_fh[idx] = *(uint32_t*)&h;
}

// ============================================================
// K3: implicit-GEMM fp16 conv, m32n64 warp tiles, FULL filter set
// resident (73.7KB), 2 CTAs/SM. Warp-decoupled x pipeline.
// ============================================================
__global__ void __launch_bounds__(256, 2)
conv_kernel() {
    extern __shared__ __align__(128) unsigned char dynsm[];
    const uint32_t smb = (uint32_t)__cvta_generic_to_shared(dynsm);
    const uint32_t mbF = smb + SMB;
    const uint32_t mbX = smb + SMB + 8;    // [2]
    const uint32_t mbC = smb + SMB + 24;   // [2], count 8

    const int tid = threadIdx.x;
    const int w = tid >> 5, lane = tid & 31;
    const int tig = lane & 3, grp = lane >> 2;
    const int row_w = w >> 1, col32 = (w & 1) * 32;
    const int b  = blockIdx.z;
    const int y0 = blockIdx.x * 4;

    const int pixoff  = ((lane >> 3) & 1) * 8 + (lane & 7);
    const int halfbit = (lane >> 4) & 1;
    // B lane: kh=(lane>>3)&1 -> <<10 (64n*16B), n=((lane>>4)&1)*8+(lane&7)
    const uint32_t blane = (((lane >> 3) & 1) << 10) +
                           (((lane >> 4) & 1)*8 + (lane & 7)) * 16;

    float acc[2][8][4];
    float s[8], q[8];
    #pragma unroll
    for (int g = 0; g < 8; g++) { s[g] = 0.f; q[g] = 0.f; }

    if (tid == 0) {
        mbar_init(mbF, 1);
        mbar_init(mbX, 1);     mbar_init(mbX + 8, 1);
        mbar_init(mbC, 8);     mbar_init(mbC + 8, 8);
    }
    __syncthreads();

    auto stage_x = [&](int step, int buf) {   // single-thread
        int t = step >> 2, cc = step & 3;
        uint32_t bar = mbX + buf*8;
        mbar_expect(bar, SXHB);
        const __half* xs = g_xh +
            ((size_t)(b*4+cc)*PPLANE + (size_t)y0*WP + t*64)*16;
        #pragma unroll
        for (int r = 0; r < 6; r++)
            bulk_cp(smb + SX0 + buf*SXHB + r*2304, xs + (size_t)r*WP*16, 2304, bar);
    };

    if (tid == 0) {
        mbar_expect(mbF, SFB);
        const uint32_t* fsrc = g_fh + (size_t)b*18432;
        #pragma unroll
        for (int cc = 0; cc < 4; cc++)
            bulk_cp(smb + cc*18432, fsrc + cc*4608, 18432, mbF);
        stage_x(0, 0);
        stage_x(1, 1);       // depth-2 prefetch
    }
    mbar_wait(mbF, 0);

    for (int step = 0; step < NSTEP; step++) {
        const int cc = step & 3, tile = step >> 2, buf = step & 1;
        const int ph = (step >> 1) & 1;
        if (cc == 0) {
            #pragma unroll
            for (int mt = 0; mt < 2; mt++)
                #pragma unroll
                for (int nt = 0; nt < 8; nt++)
                    #pragma unroll
                    for (int r = 0; r < 4; r++) acc[mt][nt][r] = 0.f;
        }
        mbar_wait(mbX + buf*8, ph);

        // ---- compute chunk: 9 taps, m32 x n64 ----
        {
            const uint32_t sxa = smb + SX0 + buf*SXHB;
            const uint32_t sba = smb + cc*18432 + blane;
            #pragma unroll
            for (int tap = 0; tap < 9; tap++) {
                const int tg = tap / 3, tloc = tap - tg*3;
                const int P = (row_w + tg)*72 + col32 + 3 + tloc + pixoff;
                uint32_t a[2][4];
                #pragma unroll
                for (int mt = 0; mt < 2; mt++) {
                    int pix = P + mt*16;
                    ldsm4(a[mt], sxa + pix*32 + (((halfbit ^ (pix >> 2)) & 1) << 4));
                }
                uint32_t bfr[16];
                const uint32_t bp = sba + tap*2048;
                ldsm4(bfr,      bp);
                ldsm4(bfr + 4,  bp + 256);
                ldsm4(bfr + 8,  bp + 512);
                ldsm4(bfr + 12, bp + 768);
                #pragma unroll
                for (int mt = 0; mt < 2; mt++)
                    #pragma unroll
                    for (int nt = 0; nt < 8; nt++)
                        mma16(acc[mt][nt], a[mt], &bfr[nt*2]);
            }
        }

        if (lane == 0) mbar_arrive(mbC + buf*8);

        if (cc == 3) {   // tile epilogue: fp16 raw y + GN partials
            __half* ob = g_yh + (size_t)b*CO*PLANE + (y0 + row_w)*WW;
            const int x0 = tile*64;
            #pragma unroll
            for (int mt = 0; mt < 2; mt++) {
                #pragma unroll
                for (int nt = 0; nt < 8; nt++) {
                    #pragma unroll
                    for (int r = 0; r < 4; r++) {
                        float v = acc[mt][nt][r];
                        int gx = x0 + col32 + mt*16 + grp + ((r >> 1) << 3);
                        int co = nt*8 + tig*2 + (r & 1);
                        ob[co*PLANE + gx] = __float2half_rn(v);
                        s[nt] += v;
                        q[nt] += v*v;
                    }
                }
            }
        }

        if (tid == 0 && step + 2 < NSTEP) {
            mbar_wait(mbC + buf*8, ph);
            stage_x(step + 2, buf);
        }
    }

    // ---- GN partial reduction (once, over all 3 tiles) ----
    #pragma unroll
    for (int o = 16; o > 0; o >>= 1) {
        #pragma unroll
        for (int g = 0; g < 8; g++) {
            s[g] += __shfl_down_sync(~0u, s[g], o);
            q[g] += __shfl_down_sync(~0u, q[g], o);
        }
    }
    if (lane == 0) {
        #pragma unroll
        for (int g = 0; g < 8; g++) {
            atomicAdd(&g_stats[b][g][0], s[g]);
            atomicAdd(&g_stats[b][g][1], q[g]);
        }
    }
}

// ============================================================
// K4: GroupNorm + affine + LeakyReLU, fp16 in -> fp32 out (R14 form)
// ============================================================
__global__ void __launch_bounds__(256)
norm_kernel(float* __restrict__ out,
            const float* __restrict__ gamma,
            const float* __restrict__ beta) {
    int idx = blockIdx.x * 256 + threadIdx.x;   // 8-px unit
    const int PL8 = PLANE / 8;
    int clin = idx / PL8;
    int r    = idx - clin*PL8;
    int co = clin & 63;
    int b  = clin >> 6;
    int g  = co >> 3;
    float s = g_stats[b][g][0], q = g_stats[b][g][1];
    const float invN = 1.f / (float)(CPG * PLANE);
    float mean = s * invN;
    float var  = q * invN - mean*mean;
    float rstd = rsqrtf(var + EPS);
    float ga = gamma[co] * rstd, be = beta[co] - mean*ga;

    uint4 v = ((const uint4*)(g_yh + (size_t)clin*PLANE))[r];
    const uint32_t* pv = (const uint32_t*)&v;
    float4 o0, o1;
    __half2 h0 = *(const __half2*)&pv[0];
    __half2 h1 = *(const __half2*)&pv[1];
    __half2 h2 = *(const __half2*)&pv[2];
    __half2 h3 = *(const __half2*)&pv[3];
    float2 f0 = __half22float2(h0), f1 = __half22float2(h1);
    float2 f2 = __half22float2(h2), f3 = __half22float2(h3);
    float y;
    y = f0.x*ga + be; o0.x = y >= 0.f ? y : SLOPE*y;
    y = f0.y*ga + be; o0.y = y >= 0.f ? y : SLOPE*y;
    y = f1.x*ga + be; o0.z = y >= 0.f ? y : SLOPE*y;
    y = f1.y*ga + be; o0.w = y >= 0.f ? y : SLOPE*y;
    y = f2.x*ga + be; o1.x = y >= 0.f ? y : SLOPE*y;
    y = f2.y*ga + be; o1.y = y >= 0.f ? y : SLOPE*y;
    y = f3.x*ga + be; o1.z = y >= 0.f ? y : SLOPE*y;
    y = f3.y*ga + be; o1.w = y >= 0.f ? y : SLOPE*y;
    float4* op = (float4*)(out + (size_t)clin*PLANE) + r*2;
    op[0] = o0;
    op[1] = o1;
}

// ============================================================
extern "C" void kernel_launch(void* const* d_in, const int* in_sizes, int n_in,
                              void* d_out, int out_size) {
    const float* x  = (const float*)d_in[0];
    const float* w1 = (const float*)d_in[1];
    const float* w2 = (const float*)d_in[2];
    const float* b2 = (const float*)d_in[3];
    const float* W  = (const float*)d_in[4];
    const float* ga = (const float*)d_in[5];
    const float* be = (const float*)d_in[6];
    float* out = (float*)d_out;

    cudaFuncSetAttribute(conv_kernel,
                         cudaFuncAttributeMaxDynamicSharedMemorySize, SMEM_DYN);

    convert_pool_kernel<<<dim3(36, 4, B), 256>>>(x);
    filt_kernel<<<(B*4*9*2*64*4)/256, 256>>>(W, w1, w2, b2);
    conv_kernel<<<dim3(48, 1, B), 256, SMEM_DYN>>>();
    norm_kernel<<<(B*CO*PLANE/8)/256, 256>>>(out, ga, be);
}